// round 1
// baseline (speedup 1.0000x reference)
#include <cuda_runtime.h>
#include <cuda_bf16.h>
#include <cstdint>

// ---------------------------------------------------------------------------
// ToFace_Unet_Dwt_locate: fused db2 channel-DWT (hi half only) -> db2 DWT ->
// [2x7] conv -> MLP 90->128->256.
//
// Shapes:
//   x:      [16, 360, 64, 64] f32
//   conv_w: [1,1,2,7], conv_b: [1]
//   w1: [128,90], b1: [128], w2: [256,128], b2: [256]
//   out: 65536 x 256 f32 (== [1024,256,8,8] flat)
//
// Stage 1 (dwt_kernel): per pixel (b,h,w), along channel axis:
//   hi1[j] = sum_i H1[i]*x[2j+i-2]            (j=0..179, zero-pad)
//   F[b, c,    hw] = sum_i H0[i]*hi1[2c+i-2]  (c=0..89)
//   F[b, 90+c, hw] = sum_i H1[i]*hi1[2c+i-2]
// F flattened [16*180*64*64] is re-chunked into 65536 chunks of 180.
//
// Stage 2 (mlp_kernel): per chunk n: row0=F[180n..+90), row1=F[180n+90..+180)
//   A[j]  = relu(cb + sum_kw w0[kw]*row0[j+kw-3] + w1c[kw]*row1[j+kw-3])
//   H     = relu(A @ W1^T + b1)   (90 -> 128)
//   Y     = H @ W2^T + b2         (128 -> 256) -> out
// ---------------------------------------------------------------------------

// db2 filters (DEC_LO / DEC_HI reversed, matching the reference)
#define H0_0 0.48296291314469025f
#define H0_1 0.836516303737469f
#define H0_2 0.22414386804185735f
#define H0_3 (-0.12940952255092145f)
#define H1_0 0.12940952255092145f
#define H1_1 (-0.22414386804185735f)
#define H1_2 0.836516303737469f
#define H1_3 (-0.48296291314469025f)

#define B_DIM 16
#define C_IN 360
#define HW 4096
#define C_MID 180          // channels of F
#define NCHUNK 65536
#define TM 64              // chunks per block in mlp_kernel

__device__ float g_F[(size_t)B_DIM * C_MID * HW];   // 47.2 MB scratch

// ---------------------------------------------------------------------------
// Kernel 1: fused double DWT along channels. grid (16, 16, 6), block 256.
//   blockIdx.x -> hw tile (256 pixels), blockIdx.y -> b, blockIdx.z -> c0/15
// Each thread produces 15 output channel-pairs (30 F values) for one pixel.
// ---------------------------------------------------------------------------
__global__ void __launch_bounds__(256) dwt_kernel(const float* __restrict__ X)
{
    const int hw = blockIdx.x * 256 + threadIdx.x;
    const int b  = blockIdx.y;
    const int c0 = blockIdx.z * 15;

    const float* Xp = X + (size_t)b * C_IN * HW + hw;

    // hi1 window: need hi1[j] for j in [2*c0-2, 2*c0+29]
    const int jstart = 2 * c0 - 2;
    float h1v[32];

    // rolling x window: hi1[j] uses x[2j-2 .. 2j+1]
    int j = jstart;
    int cA = 2 * j - 2, cB = 2 * j - 1;
    float xm2 = (cA >= 0 && cA < C_IN) ? Xp[(size_t)cA * HW] : 0.f;
    float xm1 = (cB >= 0 && cB < C_IN) ? Xp[(size_t)cB * HW] : 0.f;
#pragma unroll
    for (int t = 0; t < 32; t++) {
        int c2j = 2 * j, c2j1 = 2 * j + 1;
        float x0 = (c2j  >= 0 && c2j  < C_IN) ? Xp[(size_t)c2j  * HW] : 0.f;
        float x1 = (c2j1 >= 0 && c2j1 < C_IN) ? Xp[(size_t)c2j1 * HW] : 0.f;
        float h = 0.f;
        if (j >= 0 && j < 180)
            h = H1_0 * xm2 + H1_1 * xm1 + H1_2 * x0 + H1_3 * x1;
        h1v[t] = h;
        xm2 = x0; xm1 = x1; j++;
    }

    float* Fp = g_F + (size_t)b * C_MID * HW + hw;
#pragma unroll
    for (int u = 0; u < 15; u++) {
        int c2 = c0 + u;
        float a = h1v[2 * u], bb = h1v[2 * u + 1], cc = h1v[2 * u + 2], dd = h1v[2 * u + 3];
        float lo = H0_0 * a + H0_1 * bb + H0_2 * cc + H0_3 * dd;
        float hi = H1_0 * a + H1_1 * bb + H1_2 * cc + H1_3 * dd;
        Fp[(size_t)c2 * HW]        = lo;
        Fp[(size_t)(90 + c2) * HW] = hi;
    }
}

// ---------------------------------------------------------------------------
// Kernel 2: conv + MLP over 65536 chunks. 1024 blocks x 256 threads,
// TM=64 chunks per block. Dynamic smem layout (floats):
//   sF  [64*180]   = 11520   raw chunk data
//   sA  [90*65]    = 5850    conv output, k-major (stride 65, conflict-free)
//   sW1 [90*129]   = 11610   W1 transposed, k-major (stride 129)
//   sH  [128*65]   = 8320    hidden, k-major (stride 65)
//   sW2 [32*257]   = 8224    W2 k-tile, k-major (stride 257)
// total 45524 floats = 182096 B
// ---------------------------------------------------------------------------
__global__ void __launch_bounds__(256) mlp_kernel(
    const float* __restrict__ cw, const float* __restrict__ cbp,
    const float* __restrict__ w1, const float* __restrict__ b1,
    const float* __restrict__ w2, const float* __restrict__ b2,
    float* __restrict__ out)
{
    extern __shared__ float s[];
    float* sF  = s;                 // 11520
    float* sA  = sF + 11520;        // 5850
    float* sW1 = sA + 5850;         // 11610
    float* sH  = sW1 + 11610;       // 8320
    float* sW2 = sH + 8320;         // 8224

    const int tid = threadIdx.x;
    const int n0  = blockIdx.x * TM;

    // ---- load F slab (64 chunks * 180 floats, fully contiguous) ----
    {
        const float4* Fv = (const float4*)(g_F + (size_t)n0 * 180);
        float4* sFv = (float4*)sF;
#pragma unroll
        for (int i = tid; i < 11520 / 4; i += 256) sFv[i] = Fv[i];
    }
    // ---- load W1 transposed: sW1[k*129 + o] = w1[o*90 + k] ----
    for (int i = tid; i < 11520; i += 256) {
        int o = i / 90, k = i - o * 90;
        sW1[k * 129 + o] = w1[i];
    }
    __syncthreads();

    // ---- conv [2x7] pad 3 + relu -> sA[j*65 + m] ----
    float c0w[7], c1w[7];
#pragma unroll
    for (int i = 0; i < 7; i++) { c0w[i] = cw[i]; c1w[i] = cw[7 + i]; }
    const float cb = cbp[0];
    for (int idx = tid; idx < TM * 90; idx += 256) {
        int m = idx / 90, jj = idx - m * 90;
        const float* r0 = sF + m * 180;
        const float* r1 = r0 + 90;
        float acc = cb;
#pragma unroll
        for (int kw = 0; kw < 7; kw++) {
            int t = jj + kw - 3;
            if (t >= 0 && t < 90) acc += c0w[kw] * r0[t] + c1w[kw] * r1[t];
        }
        sA[jj * 65 + m] = fmaxf(acc, 0.f);
    }
    __syncthreads();

    // ---- GEMM1: H[64x128] = relu(A[64x90] @ W1^T + b1) ----
    const int tm = tid & 15, tn = tid >> 4;
    const int ms = tm * 4, ns = tn * 8;
    float acc1[4][8];
#pragma unroll
    for (int i = 0; i < 4; i++)
#pragma unroll
        for (int jx = 0; jx < 8; jx++) acc1[i][jx] = 0.f;

    for (int k = 0; k < 90; k++) {
        const float* ap = sA + k * 65 + ms;
        float a0 = ap[0], a1 = ap[1], a2 = ap[2], a3 = ap[3];
        const float* wr = sW1 + k * 129 + ns;
#pragma unroll
        for (int jx = 0; jx < 8; jx++) {
            float w = wr[jx];
            acc1[0][jx] += a0 * w; acc1[1][jx] += a1 * w;
            acc1[2][jx] += a2 * w; acc1[3][jx] += a3 * w;
        }
    }
#pragma unroll
    for (int jx = 0; jx < 8; jx++) {
        float bv = b1[ns + jx];
#pragma unroll
        for (int i = 0; i < 4; i++)
            sH[(ns + jx) * 65 + ms + i] = fmaxf(acc1[i][jx] + bv, 0.f);
    }
    __syncthreads();

    // ---- GEMM2: Y[64x256] = H[64x128] @ W2^T + b2, K tiled by 32 ----
    const int ns2 = (tid >> 4) * 16;
    float acc2[4][16];
#pragma unroll
    for (int i = 0; i < 4; i++)
#pragma unroll
        for (int jx = 0; jx < 16; jx++) acc2[i][jx] = 0.f;

    for (int kt = 0; kt < 4; kt++) {
        // load W2 tile: sW2[kk*257 + n] = w2[n*128 + kt*32 + kk]
        for (int i = tid; i < 8192; i += 256) {
            int n = i >> 5, kk = i & 31;
            sW2[kk * 257 + n] = w2[n * 128 + kt * 32 + kk];
        }
        __syncthreads();
        for (int kk = 0; kk < 32; kk++) {
            const float* hp = sH + (kt * 32 + kk) * 65 + ms;
            float h0 = hp[0], h1 = hp[1], h2 = hp[2], h3 = hp[3];
            const float* wr = sW2 + kk * 257 + ns2;
#pragma unroll
            for (int jx = 0; jx < 16; jx++) {
                float w = wr[jx];
                acc2[0][jx] += h0 * w; acc2[1][jx] += h1 * w;
                acc2[2][jx] += h2 * w; acc2[3][jx] += h3 * w;
            }
        }
        __syncthreads();
    }

    // ---- epilogue: + b2, write out ----
    float bv[16];
#pragma unroll
    for (int jx = 0; jx < 16; jx++) bv[jx] = b2[ns2 + jx];
#pragma unroll
    for (int i = 0; i < 4; i++) {
        float4 v[4];
        float* vf = (float*)v;
#pragma unroll
        for (int jx = 0; jx < 16; jx++) vf[jx] = acc2[i][jx] + bv[jx];
        float4* op = (float4*)(out + (size_t)(n0 + ms + i) * 256 + ns2);
        op[0] = v[0]; op[1] = v[1]; op[2] = v[2]; op[3] = v[3];
    }
}

// ---------------------------------------------------------------------------
extern "C" void kernel_launch(void* const* d_in, const int* in_sizes, int n_in,
                              void* d_out, int out_size)
{
    const float* x      = (const float*)d_in[0];
    const float* conv_w = (const float*)d_in[1];
    const float* conv_b = (const float*)d_in[2];
    const float* w1     = (const float*)d_in[3];
    const float* b1     = (const float*)d_in[4];
    const float* w2     = (const float*)d_in[5];
    const float* b2     = (const float*)d_in[6];
    float* out = (float*)d_out;

    (void)in_sizes; (void)n_in; (void)out_size;

    // Stage 1: double DWT -> g_F
    dim3 g1(HW / 256, B_DIM, 6);
    dwt_kernel<<<g1, 256>>>(x);

    // Stage 2: conv + MLP
    const int smem_bytes = 45524 * (int)sizeof(float);   // 182096
    cudaFuncSetAttribute(mlp_kernel, cudaFuncAttributeMaxDynamicSharedMemorySize,
                         smem_bytes);
    mlp_kernel<<<NCHUNK / TM, 256, smem_bytes>>>(conv_w, conv_b, w1, b1, w2, b2, out);
}

// round 3
// speedup vs baseline: 1.4399x; 1.4399x over previous
#include <cuda_runtime.h>
#include <cuda_bf16.h>
#include <cstdint>

// ---------------------------------------------------------------------------
// ToFace_Unet_Dwt_locate: fused db2 channel-DWT (hi half only) -> db2 DWT ->
// [2x7] conv -> MLP 90->128->256.
//
// R3: same as R2 (smem 182KB -> 115.6KB via aliasing + W1 pre-transpose, so
// 2 CTAs/SM) but with region C base rounded to a 16B boundary (17376 floats)
// to fix the misaligned float4 access.
// ---------------------------------------------------------------------------

// db2 filters (DEC_LO / DEC_HI reversed, matching the reference)
#define H0_0 0.48296291314469025f
#define H0_1 0.836516303737469f
#define H0_2 0.22414386804185735f
#define H0_3 (-0.12940952255092145f)
#define H1_0 0.12940952255092145f
#define H1_1 (-0.22414386804185735f)
#define H1_2 0.836516303737469f
#define H1_3 (-0.48296291314469025f)

#define B_DIM 16
#define C_IN 360
#define HW 4096
#define C_MID 180
#define NCHUNK 65536
#define TM 64

#define REGC_BASE 17376          // 16B-aligned region C base (floats)
#define SMEM_FLOATS (REGC_BASE + 11520)   // 28896 floats = 115584 B

__device__ float g_F[(size_t)B_DIM * C_MID * HW];   // 47.2 MB scratch
__device__ float g_W1T[90 * 128];                   // W1 transposed, k-major

// ---------------------------------------------------------------------------
// Kernel 0: transpose W1 [128,90] -> [90,128]
// ---------------------------------------------------------------------------
__global__ void w1t_kernel(const float* __restrict__ w1)
{
    int i = blockIdx.x * 256 + threadIdx.x;          // i = o*90 + k
    if (i < 11520) {
        int o = i / 90, k = i - o * 90;
        g_W1T[k * 128 + o] = w1[i];
    }
}

// ---------------------------------------------------------------------------
// Kernel 1: fused double DWT along channels. grid (16, 16, 6), block 256.
// ---------------------------------------------------------------------------
__global__ void __launch_bounds__(256) dwt_kernel(const float* __restrict__ X)
{
    const int hw = blockIdx.x * 256 + threadIdx.x;
    const int b  = blockIdx.y;
    const int c0 = blockIdx.z * 15;

    const float* Xp = X + (size_t)b * C_IN * HW + hw;

    const int jstart = 2 * c0 - 2;
    float h1v[32];

    int j = jstart;
    int cA = 2 * j - 2, cB = 2 * j - 1;
    float xm2 = (cA >= 0 && cA < C_IN) ? Xp[(size_t)cA * HW] : 0.f;
    float xm1 = (cB >= 0 && cB < C_IN) ? Xp[(size_t)cB * HW] : 0.f;
#pragma unroll
    for (int t = 0; t < 32; t++) {
        int c2j = 2 * j, c2j1 = 2 * j + 1;
        float x0 = (c2j  >= 0 && c2j  < C_IN) ? Xp[(size_t)c2j  * HW] : 0.f;
        float x1 = (c2j1 >= 0 && c2j1 < C_IN) ? Xp[(size_t)c2j1 * HW] : 0.f;
        float h = 0.f;
        if (j >= 0 && j < 180)
            h = H1_0 * xm2 + H1_1 * xm1 + H1_2 * x0 + H1_3 * x1;
        h1v[t] = h;
        xm2 = x0; xm1 = x1; j++;
    }

    float* Fp = g_F + (size_t)b * C_MID * HW + hw;
#pragma unroll
    for (int u = 0; u < 15; u++) {
        int c2 = c0 + u;
        float a = h1v[2 * u], bb = h1v[2 * u + 1], cc = h1v[2 * u + 2], dd = h1v[2 * u + 3];
        float lo = H0_0 * a + H0_1 * bb + H0_2 * cc + H0_3 * dd;
        float hi = H1_0 * a + H1_1 * bb + H1_2 * cc + H1_3 * dd;
        Fp[(size_t)c2 * HW]        = lo;
        Fp[(size_t)(90 + c2) * HW] = hi;
    }
}

// ---------------------------------------------------------------------------
// Kernel 2: conv + MLP over 65536 chunks. 1024 blocks x 256 threads.
// Dynamic smem (floats), with temporal aliasing:
//   region A [0 .. 11520):          sF [64*180]       then sH [128*65]=8320
//   region B [11520 .. 17370):      sA [90*65]=5850
//   region C [17376 .. 28896):      sW1 [90*128]=11520 then sW2 [32*257]=8224
// total 28896 floats = 115584 B -> 2 CTAs/SM.
// ---------------------------------------------------------------------------
__global__ void __launch_bounds__(256, 2) mlp_kernel(
    const float* __restrict__ cw, const float* __restrict__ cbp,
    const float* __restrict__ b1,
    const float* __restrict__ w2, const float* __restrict__ b2,
    float* __restrict__ out)
{
    extern __shared__ float s[];
    float* sF  = s;                 // region A (phase 0-1)
    float* sH  = s;                 // region A (phase 2-3)
    float* sA  = s + 11520;         // region B
    float* sW1 = s + REGC_BASE;     // region C (phase 0-2)
    float* sW2 = s + REGC_BASE;     // region C (phase 3)

    const int tid = threadIdx.x;
    const int n0  = blockIdx.x * TM;

    // ---- load F slab (contiguous) and W1T (contiguous copy) ----
    {
        const float4* Fv = (const float4*)(g_F + (size_t)n0 * 180);
        float4* sFv = (float4*)sF;
#pragma unroll
        for (int i = tid; i < 11520 / 4; i += 256) sFv[i] = Fv[i];
        const float4* Wv = (const float4*)g_W1T;
        float4* sWv = (float4*)sW1;
#pragma unroll
        for (int i = tid; i < 11520 / 4; i += 256) sWv[i] = Wv[i];
    }
    __syncthreads();

    // ---- conv [2x7] pad 3 + relu -> sA[j*65 + m] ----
    float c0w[7], c1w[7];
#pragma unroll
    for (int i = 0; i < 7; i++) { c0w[i] = cw[i]; c1w[i] = cw[7 + i]; }
    const float cb = cbp[0];
    for (int idx = tid; idx < TM * 90; idx += 256) {
        int m = idx / 90, jj = idx - m * 90;
        const float* r0 = sF + m * 180;
        const float* r1 = r0 + 90;
        float acc = cb;
#pragma unroll
        for (int kw = 0; kw < 7; kw++) {
            int t = jj + kw - 3;
            if (t >= 0 && t < 90) acc += c0w[kw] * r0[t] + c1w[kw] * r1[t];
        }
        sA[jj * 65 + m] = fmaxf(acc, 0.f);
    }
    __syncthreads();   // sF dead after this point; region A becomes sH

    // ---- GEMM1: H[64x128] = relu(A[64x90] @ W1^T + b1) ----
    const int tm = tid & 15, tn = tid >> 4;
    const int ms = tm * 4, ns = tn * 8;
    float acc1[4][8];
#pragma unroll
    for (int i = 0; i < 4; i++)
#pragma unroll
        for (int jx = 0; jx < 8; jx++) acc1[i][jx] = 0.f;

#pragma unroll 2
    for (int k = 0; k < 90; k++) {
        const float* ap = sA + k * 65 + ms;
        float a0 = ap[0], a1 = ap[1], a2 = ap[2], a3 = ap[3];
        const float* wr = sW1 + k * 128 + ns;
#pragma unroll
        for (int jx = 0; jx < 8; jx++) {
            float w = wr[jx];
            acc1[0][jx] += a0 * w; acc1[1][jx] += a1 * w;
            acc1[2][jx] += a2 * w; acc1[3][jx] += a3 * w;
        }
    }
#pragma unroll
    for (int jx = 0; jx < 8; jx++) {
        float bv = b1[ns + jx];
#pragma unroll
        for (int i = 0; i < 4; i++)
            sH[(ns + jx) * 65 + ms + i] = fmaxf(acc1[i][jx] + bv, 0.f);
    }
    __syncthreads();   // sW1 dead after this; region C becomes sW2

    // ---- GEMM2: Y[64x256] = H[64x128] @ W2^T + b2, K tiled by 32 ----
    const int ns2 = (tid >> 4) * 16;
    float acc2[4][16];
#pragma unroll
    for (int i = 0; i < 4; i++)
#pragma unroll
        for (int jx = 0; jx < 16; jx++) acc2[i][jx] = 0.f;

    for (int kt = 0; kt < 4; kt++) {
        // load W2 tile: sW2[kk*257 + n] = w2[n*128 + kt*32 + kk] (coalesced read,
        // stride-257 write = conflict-free)
        for (int i = tid; i < 8192; i += 256) {
            int n = i >> 5, kk = i & 31;
            sW2[kk * 257 + n] = w2[n * 128 + kt * 32 + kk];
        }
        __syncthreads();
#pragma unroll 2
        for (int kk = 0; kk < 32; kk++) {
            const float* hp = sH + (kt * 32 + kk) * 65 + ms;
            float h0 = hp[0], h1 = hp[1], h2 = hp[2], h3 = hp[3];
            const float* wr = sW2 + kk * 257 + ns2;
#pragma unroll
            for (int jx = 0; jx < 16; jx++) {
                float w = wr[jx];
                acc2[0][jx] += h0 * w; acc2[1][jx] += h1 * w;
                acc2[2][jx] += h2 * w; acc2[3][jx] += h3 * w;
            }
        }
        __syncthreads();
    }

    // ---- epilogue: + b2, write out ----
    float bv[16];
#pragma unroll
    for (int jx = 0; jx < 16; jx++) bv[jx] = b2[ns2 + jx];
#pragma unroll
    for (int i = 0; i < 4; i++) {
        float4 v[4];
        float* vf = (float*)v;
#pragma unroll
        for (int jx = 0; jx < 16; jx++) vf[jx] = acc2[i][jx] + bv[jx];
        float4* op = (float4*)(out + (size_t)(n0 + ms + i) * 256 + ns2);
        op[0] = v[0]; op[1] = v[1]; op[2] = v[2]; op[3] = v[3];
    }
}

// ---------------------------------------------------------------------------
extern "C" void kernel_launch(void* const* d_in, const int* in_sizes, int n_in,
                              void* d_out, int out_size)
{
    const float* x      = (const float*)d_in[0];
    const float* conv_w = (const float*)d_in[1];
    const float* conv_b = (const float*)d_in[2];
    const float* w1     = (const float*)d_in[3];
    const float* b1     = (const float*)d_in[4];
    const float* w2     = (const float*)d_in[5];
    const float* b2     = (const float*)d_in[6];
    float* out = (float*)d_out;

    (void)in_sizes; (void)n_in; (void)out_size;

    // Stage 0: transpose W1 (tiny)
    w1t_kernel<<<45, 256>>>(w1);

    // Stage 1: double DWT -> g_F
    dim3 g1(HW / 256, B_DIM, 6);
    dwt_kernel<<<g1, 256>>>(x);

    // Stage 2: conv + MLP (2 CTAs/SM)
    const int smem_bytes = SMEM_FLOATS * (int)sizeof(float);   // 115584 B
    cudaFuncSetAttribute(mlp_kernel, cudaFuncAttributeMaxDynamicSharedMemorySize,
                         smem_bytes);
    mlp_kernel<<<NCHUNK / TM, 256, smem_bytes>>>(conv_w, conv_b, b1, w2, b2, out);
}

// round 4
// speedup vs baseline: 1.5267x; 1.0603x over previous
#include <cuda_runtime.h>
#include <cuda_bf16.h>
#include <cstdint>

// ---------------------------------------------------------------------------
// ToFace_Unet_Dwt_locate: fused db2 channel-DWT (hi half only) -> db2 DWT ->
// [2x7] conv -> MLP 90->128->256.
//
// R4: packed f32x2 FMA (FFMA2) in both GEMMs via PTX fma.rn.f32x2 — 2 fp32
// FMAs per issued instruction at full fp32 precision. W2 smem stride 257->258
// for 8B-aligned 64-bit weight-pair loads. w1t transpose folded into
// dwt_kernel grid-z slice 6.
// ---------------------------------------------------------------------------

// db2 filters (DEC_LO / DEC_HI reversed, matching the reference)
#define H0_0 0.48296291314469025f
#define H0_1 0.836516303737469f
#define H0_2 0.22414386804185735f
#define H0_3 (-0.12940952255092145f)
#define H1_0 0.12940952255092145f
#define H1_1 (-0.22414386804185735f)
#define H1_2 0.836516303737469f
#define H1_3 (-0.48296291314469025f)

#define B_DIM 16
#define C_IN 360
#define HW 4096
#define C_MID 180
#define NCHUNK 65536
#define TM 64

#define REGC_BASE 17376                   // 16B-aligned region C base (floats)
#define SMEM_FLOATS (REGC_BASE + 11520)   // 28896 floats = 115584 B

__device__ float g_F[(size_t)B_DIM * C_MID * HW];   // 47.2 MB scratch
__device__ float g_W1T[90 * 128];                   // W1 transposed, k-major

// ---- packed f32x2 helpers -------------------------------------------------
__device__ __forceinline__ unsigned long long pk2(float lo, float hi) {
    unsigned long long r;
    asm("mov.b64 %0, {%1, %2};" : "=l"(r) : "f"(lo), "f"(hi));
    return r;
}
__device__ __forceinline__ void upk2(float& lo, float& hi, unsigned long long v) {
    asm("mov.b64 {%0, %1}, %2;" : "=f"(lo), "=f"(hi) : "l"(v));
}
__device__ __forceinline__ void fma2(unsigned long long& d,
                                     unsigned long long a, unsigned long long b) {
    asm("fma.rn.f32x2 %0, %1, %2, %0;" : "+l"(d) : "l"(a), "l"(b));
}

// ---------------------------------------------------------------------------
// Kernel 1: fused double DWT along channels + W1 transpose side-job.
// grid (16, 16, 7), block 256. z<6: DWT (z -> c0 block). z==6: W1 transpose.
// ---------------------------------------------------------------------------
__global__ void __launch_bounds__(256) dwt_kernel(const float* __restrict__ X,
                                                  const float* __restrict__ w1)
{
    if (blockIdx.z == 6) {
        int i = (blockIdx.y * 16 + blockIdx.x) * 256 + threadIdx.x;
        if (i < 11520) {
            int o = i / 90, k = i - o * 90;
            g_W1T[k * 128 + o] = w1[i];
        }
        return;
    }

    const int hw = blockIdx.x * 256 + threadIdx.x;
    const int b  = blockIdx.y;
    const int c0 = blockIdx.z * 15;

    const float* Xp = X + (size_t)b * C_IN * HW + hw;

    const int jstart = 2 * c0 - 2;
    float h1v[32];

    int j = jstart;
    int cA = 2 * j - 2, cB = 2 * j - 1;
    float xm2 = (cA >= 0 && cA < C_IN) ? Xp[(size_t)cA * HW] : 0.f;
    float xm1 = (cB >= 0 && cB < C_IN) ? Xp[(size_t)cB * HW] : 0.f;
#pragma unroll
    for (int t = 0; t < 32; t++) {
        int c2j = 2 * j, c2j1 = 2 * j + 1;
        float x0 = (c2j  >= 0 && c2j  < C_IN) ? Xp[(size_t)c2j  * HW] : 0.f;
        float x1 = (c2j1 >= 0 && c2j1 < C_IN) ? Xp[(size_t)c2j1 * HW] : 0.f;
        float h = 0.f;
        if (j >= 0 && j < 180)
            h = H1_0 * xm2 + H1_1 * xm1 + H1_2 * x0 + H1_3 * x1;
        h1v[t] = h;
        xm2 = x0; xm1 = x1; j++;
    }

    float* Fp = g_F + (size_t)b * C_MID * HW + hw;
#pragma unroll
    for (int u = 0; u < 15; u++) {
        int c2 = c0 + u;
        float a = h1v[2 * u], bb = h1v[2 * u + 1], cc = h1v[2 * u + 2], dd = h1v[2 * u + 3];
        float lo = H0_0 * a + H0_1 * bb + H0_2 * cc + H0_3 * dd;
        float hi = H1_0 * a + H1_1 * bb + H1_2 * cc + H1_3 * dd;
        Fp[(size_t)c2 * HW]        = lo;
        Fp[(size_t)(90 + c2) * HW] = hi;
    }
}

// ---------------------------------------------------------------------------
// Kernel 2: conv + MLP over 65536 chunks. 1024 blocks x 256 threads.
// Dynamic smem (floats), temporal aliasing:
//   region A [0 .. 11520):          sF [64*180]       then sH [128*65]=8320
//   region B [11520 .. 17370):      sA [90*65]=5850
//   region C [17376 .. 28896):      sW1 [90*128]=11520 then sW2 [32*258]=8256
// total 28896 floats = 115584 B -> 2 CTAs/SM.
// ---------------------------------------------------------------------------
__global__ void __launch_bounds__(256, 2) mlp_kernel(
    const float* __restrict__ cw, const float* __restrict__ cbp,
    const float* __restrict__ b1,
    const float* __restrict__ w2, const float* __restrict__ b2,
    float* __restrict__ out)
{
    extern __shared__ float s[];
    float* sF  = s;                 // region A (phase 0-1)
    float* sH  = s;                 // region A (phase 2-3)
    float* sA  = s + 11520;         // region B
    float* sW1 = s + REGC_BASE;     // region C (phase 0-2)
    float* sW2 = s + REGC_BASE;     // region C (phase 3)

    const int tid = threadIdx.x;
    const int n0  = blockIdx.x * TM;

    // ---- load F slab (contiguous) and W1T (contiguous copy) ----
    {
        const float4* Fv = (const float4*)(g_F + (size_t)n0 * 180);
        float4* sFv = (float4*)sF;
#pragma unroll
        for (int i = tid; i < 11520 / 4; i += 256) sFv[i] = Fv[i];
        const float4* Wv = (const float4*)g_W1T;
        float4* sWv = (float4*)sW1;
#pragma unroll
        for (int i = tid; i < 11520 / 4; i += 256) sWv[i] = Wv[i];
    }
    __syncthreads();

    // ---- conv [2x7] pad 3 + relu -> sA[j*65 + m] ----
    float c0w[7], c1w[7];
#pragma unroll
    for (int i = 0; i < 7; i++) { c0w[i] = cw[i]; c1w[i] = cw[7 + i]; }
    const float cb = cbp[0];
    for (int idx = tid; idx < TM * 90; idx += 256) {
        int m = idx / 90, jj = idx - m * 90;
        const float* r0 = sF + m * 180;
        const float* r1 = r0 + 90;
        float acc = cb;
#pragma unroll
        for (int kw = 0; kw < 7; kw++) {
            int t = jj + kw - 3;
            if (t >= 0 && t < 90) acc += c0w[kw] * r0[t] + c1w[kw] * r1[t];
        }
        sA[jj * 65 + m] = fmaxf(acc, 0.f);
    }
    __syncthreads();   // sF dead after this point; region A becomes sH

    // ---- GEMM1: H[64x128] = relu(A[64x90] @ W1^T + b1), FFMA2 ----
    const int tm = tid & 15, tn = tid >> 4;
    const int ms = tm * 4, ns = tn * 8;
    unsigned long long acc1[4][4];   // [m][n-pair]
#pragma unroll
    for (int i = 0; i < 4; i++)
#pragma unroll
        for (int jp = 0; jp < 4; jp++) acc1[i][jp] = pk2(0.f, 0.f);

#pragma unroll 2
    for (int k = 0; k < 90; k++) {
        const float* ap = sA + k * 65 + ms;
        unsigned long long a0 = pk2(ap[0], ap[0]);
        unsigned long long a1 = pk2(ap[1], ap[1]);
        unsigned long long a2 = pk2(ap[2], ap[2]);
        unsigned long long a3 = pk2(ap[3], ap[3]);
        const unsigned long long* wr =
            (const unsigned long long*)(sW1 + k * 128 + ns);  // 8B aligned
#pragma unroll
        for (int jp = 0; jp < 4; jp++) {
            unsigned long long w = wr[jp];
            fma2(acc1[0][jp], a0, w);
            fma2(acc1[1][jp], a1, w);
            fma2(acc1[2][jp], a2, w);
            fma2(acc1[3][jp], a3, w);
        }
    }
#pragma unroll
    for (int jp = 0; jp < 4; jp++) {
        float b_lo = b1[ns + 2 * jp], b_hi = b1[ns + 2 * jp + 1];
#pragma unroll
        for (int i = 0; i < 4; i++) {
            float lo, hi;
            upk2(lo, hi, acc1[i][jp]);
            sH[(ns + 2 * jp)     * 65 + ms + i] = fmaxf(lo + b_lo, 0.f);
            sH[(ns + 2 * jp + 1) * 65 + ms + i] = fmaxf(hi + b_hi, 0.f);
        }
    }
    __syncthreads();   // sW1 dead after this; region C becomes sW2

    // ---- GEMM2: Y[64x256] = H[64x128] @ W2^T + b2, K tiled by 32, FFMA2 ----
    const int ns2 = (tid >> 4) * 16;
    unsigned long long acc2[4][8];   // [m][n-pair]
#pragma unroll
    for (int i = 0; i < 4; i++)
#pragma unroll
        for (int jp = 0; jp < 8; jp++) acc2[i][jp] = pk2(0.f, 0.f);

    for (int kt = 0; kt < 4; kt++) {
        // load W2 tile: sW2[kk*258 + n] = w2[n*128 + kt*32 + kk]
        for (int i = tid; i < 8192; i += 256) {
            int n = i >> 5, kk = i & 31;
            sW2[kk * 258 + n] = w2[n * 128 + kt * 32 + kk];
        }
        __syncthreads();
#pragma unroll 2
        for (int kk = 0; kk < 32; kk++) {
            const float* hp = sH + (kt * 32 + kk) * 65 + ms;
            unsigned long long h0 = pk2(hp[0], hp[0]);
            unsigned long long h1 = pk2(hp[1], hp[1]);
            unsigned long long h2 = pk2(hp[2], hp[2]);
            unsigned long long h3 = pk2(hp[3], hp[3]);
            const unsigned long long* wr =
                (const unsigned long long*)(sW2 + kk * 258 + ns2);  // 8B aligned
#pragma unroll
            for (int jp = 0; jp < 8; jp++) {
                unsigned long long w = wr[jp];
                fma2(acc2[0][jp], h0, w);
                fma2(acc2[1][jp], h1, w);
                fma2(acc2[2][jp], h2, w);
                fma2(acc2[3][jp], h3, w);
            }
        }
        __syncthreads();
    }

    // ---- epilogue: + b2, write out ----
    float bv[16];
#pragma unroll
    for (int jx = 0; jx < 16; jx++) bv[jx] = b2[ns2 + jx];
#pragma unroll
    for (int i = 0; i < 4; i++) {
        float4 v[4];
        float* vf = (float*)v;
#pragma unroll
        for (int jp = 0; jp < 8; jp++) {
            float lo, hi;
            upk2(lo, hi, acc2[i][jp]);
            vf[2 * jp]     = lo + bv[2 * jp];
            vf[2 * jp + 1] = hi + bv[2 * jp + 1];
        }
        float4* op = (float4*)(out + (size_t)(n0 + ms + i) * 256 + ns2);
        op[0] = v[0]; op[1] = v[1]; op[2] = v[2]; op[3] = v[3];
    }
}

// ---------------------------------------------------------------------------
extern "C" void kernel_launch(void* const* d_in, const int* in_sizes, int n_in,
                              void* d_out, int out_size)
{
    const float* x      = (const float*)d_in[0];
    const float* conv_w = (const float*)d_in[1];
    const float* conv_b = (const float*)d_in[2];
    const float* w1     = (const float*)d_in[3];
    const float* b1     = (const float*)d_in[4];
    const float* w2     = (const float*)d_in[5];
    const float* b2     = (const float*)d_in[6];
    float* out = (float*)d_out;

    (void)in_sizes; (void)n_in; (void)out_size;

    // Stage 1: double DWT -> g_F, plus W1 transpose in z-slice 6
    dim3 g1(HW / 256, B_DIM, 7);
    dwt_kernel<<<g1, 256>>>(x, w1);

    // Stage 2: conv + MLP (2 CTAs/SM)
    const int smem_bytes = SMEM_FLOATS * (int)sizeof(float);   // 115584 B
    cudaFuncSetAttribute(mlp_kernel, cudaFuncAttributeMaxDynamicSharedMemorySize,
                         smem_bytes);
    mlp_kernel<<<NCHUNK / TM, 256, smem_bytes>>>(conv_w, conv_b, b1, w2, b2, out);
}

// round 5
// speedup vs baseline: 1.8170x; 1.1902x over previous
#include <cuda_runtime.h>
#include <cuda_bf16.h>
#include <cstdint>

// ---------------------------------------------------------------------------
// ToFace_Unet_Dwt_locate: fused db2 channel-DWT (hi half only) -> db2 DWT ->
// [2x7] conv -> MLP 90->128->256.
//
// R5: LDS.128 everywhere in the GEMMs (float4 activations, ulonglong2 weight
// pairs feeding fma.rn.f32x2 directly), register-windowed conv (6 jj x 4 m
// per thread), W2 pre-transposed in the prologue, W1 staged in 2 halves so
// smem = 103.8KB -> 2 CTAs/SM.
// ---------------------------------------------------------------------------

#define H0_0 0.48296291314469025f
#define H0_1 0.836516303737469f
#define H0_2 0.22414386804185735f
#define H0_3 (-0.12940952255092145f)
#define H1_0 0.12940952255092145f
#define H1_1 (-0.22414386804185735f)
#define H1_2 0.836516303737469f
#define H1_3 (-0.48296291314469025f)

#define B_DIM 16
#define C_IN 360
#define HW 4096
#define C_MID 180
#define NCHUNK 65536
#define TM 64

// smem layout (floats), stride 68 for activation tiles (16B-aligned rows):
//   region A [0, 11520):      sF [64*180]            then sH [128*68]=8704
//   region B [11520, 17640):  sA [90*68]=6120
//   region C [17640, 25960):  sW1 half [45*128]=5760 then sW2 [32*260]=8320
#define SA_BASE   11520
#define REGC_BASE 17640
#define SMEM_FLOATS (REGC_BASE + 8320)   // 25960 floats = 103840 B

__device__ float g_F[(size_t)B_DIM * C_MID * HW];   // 47.2 MB scratch
__device__ float g_W1T[90 * 128];                   // W1 transposed, k-major
__device__ float g_W2T[128 * 256];                  // W2 transposed, k-major

// ---- packed f32x2 helpers -------------------------------------------------
__device__ __forceinline__ unsigned long long pk2(float lo, float hi) {
    unsigned long long r;
    asm("mov.b64 %0, {%1, %2};" : "=l"(r) : "f"(lo), "f"(hi));
    return r;
}
__device__ __forceinline__ void upk2(float& lo, float& hi, unsigned long long v) {
    asm("mov.b64 {%0, %1}, %2;" : "=f"(lo), "=f"(hi) : "l"(v));
}
__device__ __forceinline__ void fma2(unsigned long long& d,
                                     unsigned long long a, unsigned long long b) {
    asm("fma.rn.f32x2 %0, %1, %2, %0;" : "+l"(d) : "l"(a), "l"(b));
}

// ---------------------------------------------------------------------------
// Kernel 1: fused double DWT + weight transposes (grid-z slice 6).
// grid (16, 16, 7), block 256.
// ---------------------------------------------------------------------------
__global__ void __launch_bounds__(256) dwt_kernel(const float* __restrict__ X,
                                                  const float* __restrict__ w1,
                                                  const float* __restrict__ w2)
{
    if (blockIdx.z == 6) {
        int i = (blockIdx.y * 16 + blockIdx.x) * 256 + threadIdx.x;
        if (i < 11520) {                       // W1: [128,90] -> [90,128]
            int o = i / 90, k = i - o * 90;
            g_W1T[k * 128 + o] = w1[i];
        } else if (i < 11520 + 32768) {        // W2: [256,128] -> [128,256]
            int j = i - 11520;
            int k = j & 127, n = j >> 7;
            g_W2T[k * 256 + n] = w2[n * 128 + k];
        }
        return;
    }

    const int hw = blockIdx.x * 256 + threadIdx.x;
    const int b  = blockIdx.y;
    const int c0 = blockIdx.z * 15;

    const float* Xp = X + (size_t)b * C_IN * HW + hw;

    const int jstart = 2 * c0 - 2;
    float h1v[32];

    int j = jstart;
    int cA = 2 * j - 2, cB = 2 * j - 1;
    float xm2 = (cA >= 0 && cA < C_IN) ? Xp[(size_t)cA * HW] : 0.f;
    float xm1 = (cB >= 0 && cB < C_IN) ? Xp[(size_t)cB * HW] : 0.f;
#pragma unroll
    for (int t = 0; t < 32; t++) {
        int c2j = 2 * j, c2j1 = 2 * j + 1;
        float x0 = (c2j  >= 0 && c2j  < C_IN) ? Xp[(size_t)c2j  * HW] : 0.f;
        float x1 = (c2j1 >= 0 && c2j1 < C_IN) ? Xp[(size_t)c2j1 * HW] : 0.f;
        float h = 0.f;
        if (j >= 0 && j < 180)
            h = H1_0 * xm2 + H1_1 * xm1 + H1_2 * x0 + H1_3 * x1;
        h1v[t] = h;
        xm2 = x0; xm1 = x1; j++;
    }

    float* Fp = g_F + (size_t)b * C_MID * HW + hw;
#pragma unroll
    for (int u = 0; u < 15; u++) {
        int c2 = c0 + u;
        float a = h1v[2 * u], bb = h1v[2 * u + 1], cc = h1v[2 * u + 2], dd = h1v[2 * u + 3];
        float lo = H0_0 * a + H0_1 * bb + H0_2 * cc + H0_3 * dd;
        float hi = H1_0 * a + H1_1 * bb + H1_2 * cc + H1_3 * dd;
        Fp[(size_t)c2 * HW]        = lo;
        Fp[(size_t)(90 + c2) * HW] = hi;
    }
}

// ---------------------------------------------------------------------------
// Kernel 2: conv + MLP over 65536 chunks. 1024 blocks x 256 threads.
// ---------------------------------------------------------------------------
__global__ void __launch_bounds__(256, 2) mlp_kernel(
    const float* __restrict__ cw, const float* __restrict__ cbp,
    const float* __restrict__ b1, const float* __restrict__ b2,
    float* __restrict__ out)
{
    extern __shared__ float s[];
    float* sF  = s;                 // region A (phase 0-1)
    float* sH  = s;                 // region A (phase 3+)
    float* sA  = s + SA_BASE;       // region B
    float* sW1 = s + REGC_BASE;     // region C (GEMM1, 45-row halves)
    float* sW2 = s + REGC_BASE;     // region C (GEMM2 tiles)

    const int tid = threadIdx.x;
    const int n0  = blockIdx.x * TM;

    // ---- load F slab + W1 half 1 ----
    {
        const float4* Fv = (const float4*)(g_F + (size_t)n0 * 180);
        float4* sFv = (float4*)sF;
#pragma unroll
        for (int i = tid; i < 11520 / 4; i += 256) sFv[i] = Fv[i];
        const float4* Wv = (const float4*)g_W1T;
        float4* sWv = (float4*)sW1;
#pragma unroll
        for (int i = tid; i < 5760 / 4; i += 256) sWv[i] = Wv[i];
    }
    __syncthreads();

    // ---- conv [2x7] pad 3 + relu -> sA[jj*68 + m] ----
    // thread (mg = tid>>4, jq = tid&15): 6 jj (jq*6..+5) x 4 m (mg*4..+3)
    {
        float c0w[7], c1w[7];
#pragma unroll
        for (int i = 0; i < 7; i++) { c0w[i] = cw[i]; c1w[i] = cw[7 + i]; }
        const float cb = cbp[0];
        const int mg = tid >> 4, jq = tid & 15;
        const int jjb = jq * 6;
        if (jjb < 90) {
            float vout[6][4];
#pragma unroll
            for (int mi = 0; mi < 4; mi++) {
                const int m = mg * 4 + mi;
                const float* r0 = sF + m * 180;
                const float* r1 = r0 + 90;
                float w0[12], w1r[12];
#pragma unroll
                for (int t = 0; t < 12; t++) {
                    int idx = jjb - 3 + t;
                    bool ok = (idx >= 0 && idx < 90);
                    w0[t]  = ok ? r0[idx] : 0.f;
                    w1r[t] = ok ? r1[idx] : 0.f;
                }
#pragma unroll
                for (int u = 0; u < 6; u++) {
                    float acc = cb;
#pragma unroll
                    for (int kw = 0; kw < 7; kw++)
                        acc += c0w[kw] * w0[u + kw] + c1w[kw] * w1r[u + kw];
                    vout[u][mi] = fmaxf(acc, 0.f);
                }
            }
#pragma unroll
            for (int u = 0; u < 6; u++) {
                float4 v = make_float4(vout[u][0], vout[u][1], vout[u][2], vout[u][3]);
                *(float4*)(sA + (jjb + u) * 68 + mg * 4) = v;
            }
        }
    }
    __syncthreads();

    // ---- GEMM1: H[64x128] = relu(A[64x90] @ W1^T + b1), FFMA2 + LDS.128 ----
    const int tm = tid & 15, tn = tid >> 4;
    const int ms = tm * 4, ns = tn * 8;
    unsigned long long acc1[4][4];
#pragma unroll
    for (int i = 0; i < 4; i++)
#pragma unroll
        for (int jp = 0; jp < 4; jp++) acc1[i][jp] = pk2(0.f, 0.f);

    for (int half = 0; half < 2; half++) {
#pragma unroll 3
        for (int kr = 0; kr < 45; kr++) {
            float4 av = *(const float4*)(sA + (half * 45 + kr) * 68 + ms);
            const ulonglong2* wr = (const ulonglong2*)(sW1 + kr * 128 + ns);
            ulonglong2 wA = wr[0], wB = wr[1];
            unsigned long long a0 = pk2(av.x, av.x), a1 = pk2(av.y, av.y);
            unsigned long long a2 = pk2(av.z, av.z), a3 = pk2(av.w, av.w);
            fma2(acc1[0][0], a0, wA.x); fma2(acc1[1][0], a1, wA.x);
            fma2(acc1[2][0], a2, wA.x); fma2(acc1[3][0], a3, wA.x);
            fma2(acc1[0][1], a0, wA.y); fma2(acc1[1][1], a1, wA.y);
            fma2(acc1[2][1], a2, wA.y); fma2(acc1[3][1], a3, wA.y);
            fma2(acc1[0][2], a0, wB.x); fma2(acc1[1][2], a1, wB.x);
            fma2(acc1[2][2], a2, wB.x); fma2(acc1[3][2], a3, wB.x);
            fma2(acc1[0][3], a0, wB.y); fma2(acc1[1][3], a1, wB.y);
            fma2(acc1[2][3], a2, wB.y); fma2(acc1[3][3], a3, wB.y);
        }
        __syncthreads();
        if (half == 0) {
            // load W1 half 2
            const float4* Wv = (const float4*)(g_W1T + 5760);
            float4* sWv = (float4*)sW1;
#pragma unroll
            for (int i = tid; i < 5760 / 4; i += 256) sWv[i] = Wv[i];
            __syncthreads();
        }
    }

    // epilogue 1: relu(+b1) -> sH[n*68 + m], float4 per n-row
#pragma unroll
    for (int jp = 0; jp < 4; jp++) {
        float b_lo = b1[ns + 2 * jp], b_hi = b1[ns + 2 * jp + 1];
        float lo0, hi0, lo1, hi1, lo2, hi2, lo3, hi3;
        upk2(lo0, hi0, acc1[0][jp]); upk2(lo1, hi1, acc1[1][jp]);
        upk2(lo2, hi2, acc1[2][jp]); upk2(lo3, hi3, acc1[3][jp]);
        float4 vlo = make_float4(fmaxf(lo0 + b_lo, 0.f), fmaxf(lo1 + b_lo, 0.f),
                                 fmaxf(lo2 + b_lo, 0.f), fmaxf(lo3 + b_lo, 0.f));
        float4 vhi = make_float4(fmaxf(hi0 + b_hi, 0.f), fmaxf(hi1 + b_hi, 0.f),
                                 fmaxf(hi2 + b_hi, 0.f), fmaxf(hi3 + b_hi, 0.f));
        *(float4*)(sH + (ns + 2 * jp)     * 68 + ms) = vlo;
        *(float4*)(sH + (ns + 2 * jp + 1) * 68 + ms) = vhi;
    }
    __syncthreads();

    // ---- GEMM2: Y[64x256] = H[64x128] @ W2^T + b2, K tiles of 32 ----
    const int ns2 = (tid >> 4) * 16;
    unsigned long long acc2[4][8];
#pragma unroll
    for (int i = 0; i < 4; i++)
#pragma unroll
        for (int jp = 0; jp < 8; jp++) acc2[i][jp] = pk2(0.f, 0.f);

    for (int kt = 0; kt < 4; kt++) {
        // fill sW2 from g_W2T: contiguous float4 rows, conflict-free
        {
            const float* src = g_W2T + (size_t)kt * 32 * 256;
#pragma unroll
            for (int i = tid; i < 2048; i += 256) {
                int kk = i >> 6, c4 = (i & 63) * 4;
                *(float4*)(sW2 + kk * 260 + c4) = *(const float4*)(src + kk * 256 + c4);
            }
        }
        __syncthreads();
#pragma unroll 2
        for (int kk = 0; kk < 32; kk++) {
            float4 hv = *(const float4*)(sH + (kt * 32 + kk) * 68 + ms);
            const ulonglong2* wr = (const ulonglong2*)(sW2 + kk * 260 + ns2);
            ulonglong2 wA = wr[0], wB = wr[1], wC = wr[2], wD = wr[3];
            unsigned long long h0 = pk2(hv.x, hv.x), h1 = pk2(hv.y, hv.y);
            unsigned long long h2 = pk2(hv.z, hv.z), h3 = pk2(hv.w, hv.w);
            fma2(acc2[0][0], h0, wA.x); fma2(acc2[1][0], h1, wA.x);
            fma2(acc2[2][0], h2, wA.x); fma2(acc2[3][0], h3, wA.x);
            fma2(acc2[0][1], h0, wA.y); fma2(acc2[1][1], h1, wA.y);
            fma2(acc2[2][1], h2, wA.y); fma2(acc2[3][1], h3, wA.y);
            fma2(acc2[0][2], h0, wB.x); fma2(acc2[1][2], h1, wB.x);
            fma2(acc2[2][2], h2, wB.x); fma2(acc2[3][2], h3, wB.x);
            fma2(acc2[0][3], h0, wB.y); fma2(acc2[1][3], h1, wB.y);
            fma2(acc2[2][3], h2, wB.y); fma2(acc2[3][3], h3, wB.y);
            fma2(acc2[0][4], h0, wC.x); fma2(acc2[1][4], h1, wC.x);
            fma2(acc2[2][4], h2, wC.x); fma2(acc2[3][4], h3, wC.x);
            fma2(acc2[0][5], h0, wC.y); fma2(acc2[1][5], h1, wC.y);
            fma2(acc2[2][5], h2, wC.y); fma2(acc2[3][5], h3, wC.y);
            fma2(acc2[0][6], h0, wD.x); fma2(acc2[1][6], h1, wD.x);
            fma2(acc2[2][6], h2, wD.x); fma2(acc2[3][6], h3, wD.x);
            fma2(acc2[0][7], h0, wD.y); fma2(acc2[1][7], h1, wD.y);
            fma2(acc2[2][7], h2, wD.y); fma2(acc2[3][7], h3, wD.y);
        }
        __syncthreads();
    }

    // ---- epilogue 2: + b2, write out ----
    float bv[16];
#pragma unroll
    for (int jx = 0; jx < 16; jx++) bv[jx] = b2[ns2 + jx];
#pragma unroll
    for (int i = 0; i < 4; i++) {
        float4 v[4];
        float* vf = (float*)v;
#pragma unroll
        for (int jp = 0; jp < 8; jp++) {
            float lo, hi;
            upk2(lo, hi, acc2[i][jp]);
            vf[2 * jp]     = lo + bv[2 * jp];
            vf[2 * jp + 1] = hi + bv[2 * jp + 1];
        }
        float4* op = (float4*)(out + (size_t)(n0 + ms + i) * 256 + ns2);
        op[0] = v[0]; op[1] = v[1]; op[2] = v[2]; op[3] = v[3];
    }
}

// ---------------------------------------------------------------------------
extern "C" void kernel_launch(void* const* d_in, const int* in_sizes, int n_in,
                              void* d_out, int out_size)
{
    const float* x      = (const float*)d_in[0];
    const float* conv_w = (const float*)d_in[1];
    const float* conv_b = (const float*)d_in[2];
    const float* w1     = (const float*)d_in[3];
    const float* b1     = (const float*)d_in[4];
    const float* w2     = (const float*)d_in[5];
    const float* b2     = (const float*)d_in[6];
    float* out = (float*)d_out;

    (void)in_sizes; (void)n_in; (void)out_size;

    // Stage 1: double DWT -> g_F, plus W1/W2 transposes in z-slice 6
    dim3 g1(HW / 256, B_DIM, 7);
    dwt_kernel<<<g1, 256>>>(x, w1, w2);

    // Stage 2: conv + MLP (2 CTAs/SM)
    const int smem_bytes = SMEM_FLOATS * (int)sizeof(float);   // 103840 B
    cudaFuncSetAttribute(mlp_kernel, cudaFuncAttributeMaxDynamicSharedMemorySize,
                         smem_bytes);
    mlp_kernel<<<NCHUNK / TM, 256, smem_bytes>>>(conv_w, conv_b, b1, b2, out);
}

// round 8
// speedup vs baseline: 2.8145x; 1.5490x over previous
#include <cuda_runtime.h>
#include <cuda_bf16.h>
#include <cstdint>

// ---------------------------------------------------------------------------
// ToFace_Unet_Dwt_locate — R8: warp-level mma.sync (HMMA bf16, 3-term split).
// (tcgen05 unavailable: harness PTX target is compute_103 without 'a'.)
//   mlp kernel: 512 blocks x 512 threads, 128 chunks/block.
//   conv (fp32 SIMT) -> A = Ahi+Alo bf16
//   GEMM1 [128x128,K=96]: acc += Ahi*W1hi + Ahi*W1lo + Alo*W1hi
//   relu+b1 -> H splits -> GEMM2 [128x256,K=128] (2 N-halves) -> +b2 -> out
// ---------------------------------------------------------------------------

#define H0_0 0.48296291314469025f
#define H0_1 0.836516303737469f
#define H0_2 0.22414386804185735f
#define H0_3 (-0.12940952255092145f)
#define H1_0 0.12940952255092145f
#define H1_1 (-0.22414386804185735f)
#define H1_2 0.836516303737469f
#define H1_3 (-0.48296291314469025f)

#define B_DIM 16
#define C_IN 360
#define HW 4096
#define C_MID 180

// smem word (uint32) offsets
#define WB1    0                      // b1: 128 f32
#define WB2    128                    // b2: 256 f32
#define WA_HI  512                    // A hi  [128][52]
#define WA_LO  7168                   // A lo  [128][52]
#define WW1_HI 13824                  // W1 hi [128][52]
#define WW1_LO 20480                  // W1 lo [128][52]
#define WW2_HI 512                    // W2 stage hi [128][68] (aliases A)
#define WW2_LO 9216                   // W2 stage lo [128][68] (aliases A/W1)
#define WH_HI  27136                  // H hi [128][68]; also F staging earlier
#define WH_LO  35840                  // H lo [128][68]
#define SMEM_WORDS 44544
#define SMEM_BYTES (SMEM_WORDS * 4)   // 178176

#define A_ST  52
#define W1_ST 52
#define W2_ST 68
#define H_ST  68

__device__ float g_F[(size_t)B_DIM * C_MID * HW];   // 47.2 MB scratch
__device__ uint32_t g_W1s[12288];                   // [hl][128][48 words]
__device__ uint32_t g_W2s[32768];                   // [nh][hl][128][64 words]

// ---- helpers --------------------------------------------------------------
__device__ __forceinline__ uint32_t pack_bf16(__nv_bfloat16 lo, __nv_bfloat16 hi) {
    return ((uint32_t)__bfloat16_as_ushort(hi) << 16) | __bfloat16_as_ushort(lo);
}
__device__ __forceinline__ void split_pair(float v0, float v1,
                                           uint32_t& whi, uint32_t& wlo) {
    __nv_bfloat16 h0 = __float2bfloat16(v0);
    __nv_bfloat16 h1 = __float2bfloat16(v1);
    float r0 = v0 - __bfloat162float(h0);
    float r1 = v1 - __bfloat162float(h1);
    whi = pack_bf16(h0, h1);
    wlo = pack_bf16(__float2bfloat16(r0), __float2bfloat16(r1));
}
__device__ __forceinline__ uint32_t split_word(float v0, float v1, int hl) {
    uint32_t a, b;
    split_pair(v0, v1, a, b);
    return hl ? b : a;
}
__device__ __forceinline__ void mma16816(float* d, const uint32_t* a,
                                         const uint32_t* b) {
    asm volatile(
        "mma.sync.aligned.m16n8k16.row.col.f32.bf16.bf16.f32 "
        "{%0,%1,%2,%3}, {%4,%5,%6,%7}, {%8,%9}, {%0,%1,%2,%3};"
        : "+f"(d[0]), "+f"(d[1]), "+f"(d[2]), "+f"(d[3])
        : "r"(a[0]), "r"(a[1]), "r"(a[2]), "r"(a[3]), "r"(b[0]), "r"(b[1]));
}

// ---------------------------------------------------------------------------
// Kernel 1: DWT (z 0..5) + weight split prologue (z == 6). grid (16,16,7)x256.
// ---------------------------------------------------------------------------
__global__ void __launch_bounds__(256) dwt_kernel(const float* __restrict__ X,
                                                  const float* __restrict__ w1,
                                                  const float* __restrict__ w2)
{
    if (blockIdx.z == 6) {
        int i = (blockIdx.y * 16 + blockIdx.x) * 256 + threadIdx.x;
        if (i < 12288) {                 // W1 words: [hl][n 128][wd 48]
            int hl = i / 6144, rr = i % 6144;
            int n = rr / 48, wd = rr % 48;
            int k0 = 2 * wd;
            float v0 = (k0     < 90) ? w1[n * 90 + k0]     : 0.f;
            float v1 = (k0 + 1 < 90) ? w1[n * 90 + k0 + 1] : 0.f;
            g_W1s[i] = split_word(v0, v1, hl);
        } else if (i < 12288 + 32768) {  // W2 words: [nh][hl][n 128][wd 64]
            int j = i - 12288;
            int nh = j >> 14, r2 = j & 16383;
            int hl = r2 >> 13, r3 = r2 & 8191;
            int n = r3 >> 6, wd = r3 & 63;
            int ng = nh * 128 + n, k0 = 2 * wd;
            float v0 = w2[ng * 128 + k0];
            float v1 = w2[ng * 128 + k0 + 1];
            g_W2s[j] = split_word(v0, v1, hl);
        }
        return;
    }

    const int hw = blockIdx.x * 256 + threadIdx.x;
    const int b  = blockIdx.y;
    const int c0 = blockIdx.z * 15;

    const float* Xp = X + (size_t)b * C_IN * HW + hw;

    const int jstart = 2 * c0 - 2;
    float h1v[32];

    int j = jstart;
    int cA = 2 * j - 2, cB = 2 * j - 1;
    float xm2 = (cA >= 0 && cA < C_IN) ? Xp[(size_t)cA * HW] : 0.f;
    float xm1 = (cB >= 0 && cB < C_IN) ? Xp[(size_t)cB * HW] : 0.f;
#pragma unroll
    for (int t = 0; t < 32; t++) {
        int c2j = 2 * j, c2j1 = 2 * j + 1;
        float x0 = (c2j  >= 0 && c2j  < C_IN) ? Xp[(size_t)c2j  * HW] : 0.f;
        float x1 = (c2j1 >= 0 && c2j1 < C_IN) ? Xp[(size_t)c2j1 * HW] : 0.f;
        float h = 0.f;
        if (j >= 0 && j < 180)
            h = H1_0 * xm2 + H1_1 * xm1 + H1_2 * x0 + H1_3 * x1;
        h1v[t] = h;
        xm2 = x0; xm1 = x1; j++;
    }

    float* Fp = g_F + (size_t)b * C_MID * HW + hw;
#pragma unroll
    for (int u = 0; u < 15; u++) {
        int c2 = c0 + u;
        float a = h1v[2 * u], bb = h1v[2 * u + 1], cc = h1v[2 * u + 2], dd = h1v[2 * u + 3];
        float lo = H0_0 * a + H0_1 * bb + H0_2 * cc + H0_3 * dd;
        float hi = H1_0 * a + H1_1 * bb + H1_2 * cc + H1_3 * dd;
        Fp[(size_t)c2 * HW]        = lo;
        Fp[(size_t)(90 + c2) * HW] = hi;
    }
}

// ---------------------------------------------------------------------------
// Kernel 2: HMMA conv+MLP. 512 blocks x 512 threads, 128 chunks/block.
// ---------------------------------------------------------------------------
__global__ void __launch_bounds__(512) mlp_kernel(
    const float* __restrict__ cw, const float* __restrict__ cbp,
    const float* __restrict__ b1, const float* __restrict__ b2,
    float* __restrict__ out)
{
    extern __shared__ uint32_t sw[];
    float* b1s = (float*)(sw + WB1);
    float* b2s = (float*)(sw + WB2);

    const int tid = threadIdx.x;
    const int n0  = blockIdx.x * 128;
    const int w   = tid >> 5, l = tid & 31;
    const int wm  = w & 3, wn = w >> 2;      // 4 m-warps x 4 n-warps
    const int g   = l >> 2, kp = l & 3;      // group row / k-pair lane

    // ---- biases + W1 stage copy ----
    if (tid < 128) b1s[tid] = b1[tid];
    if (tid < 256) b2s[tid] = b2[tid];
    {
        const uint2* src = (const uint2*)g_W1s;   // [hl][128][24 uint2]
#pragma unroll
        for (int i = tid; i < 6144; i += 512) {
            int hl = i / 3072, rr = i % 3072;
            int n = rr / 24, wq = rr % 24;
            *(uint2*)(sw + (hl ? WW1_LO : WW1_HI) + n * W1_ST + 2 * wq) = src[i];
        }
    }

    // ---- conv: F staged through H region, 2 halves of 64 chunks ----
    {
        float c0w[7], c1w[7];
#pragma unroll
        for (int i = 0; i < 7; i++) { c0w[i] = cw[i]; c1w[i] = cw[7 + i]; }
        const float cb = cbp[0];
        float* sF = (float*)(sw + WH_HI);        // 64*180 floats staging
        const int ml = tid >> 3, q8 = tid & 7;

        for (int fh = 0; fh < 2; fh++) {
            const float4* src = (const float4*)(g_F + (size_t)(n0 + fh * 64) * 180);
            float4* dst = (float4*)sF;
#pragma unroll
            for (int i = tid; i < 2880; i += 512) dst[i] = src[i];
            __syncthreads();

            const float* r0 = sF + ml * 180;
            const float* r1 = r0 + 90;
            float a0[18], a1[18];
#pragma unroll
            for (int t = 0; t < 18; t++) {
                int idx = q8 * 12 - 3 + t;
                bool ok = (idx >= 0 && idx < 90);
                a0[t] = ok ? r0[idx] : 0.f;
                a1[t] = ok ? r1[idx] : 0.f;
            }
            const int mrow = fh * 64 + ml;
            uint32_t* Ah = sw + WA_HI + mrow * A_ST;
            uint32_t* Al = sw + WA_LO + mrow * A_ST;
#pragma unroll
            for (int pl = 0; pl < 6; pl++) {
                int p = q8 * 6 + pl;             // k-pair word 0..47
                float v0 = 0.f, v1 = 0.f;
                if (2 * p < 90) {
                    float s0 = cb, s1 = cb;
#pragma unroll
                    for (int kw = 0; kw < 7; kw++) {
                        s0 += c0w[kw] * a0[2 * pl + kw]     + c1w[kw] * a1[2 * pl + kw];
                        s1 += c0w[kw] * a0[2 * pl + 1 + kw] + c1w[kw] * a1[2 * pl + 1 + kw];
                    }
                    v0 = fmaxf(s0, 0.f);
                    v1 = fmaxf(s1, 0.f);
                }
                uint32_t whi, wlo;
                split_pair(v0, v1, whi, wlo);
                Ah[p] = whi;
                Al[p] = wlo;
            }
            __syncthreads();
        }
    }

    // ---- GEMM1: [128m x 128n], K=96 (6 k-steps), 3-term split ----
    float acc1[2][4][4];
#pragma unroll
    for (int mi = 0; mi < 2; mi++)
#pragma unroll
        for (int t = 0; t < 4; t++)
#pragma unroll
            for (int e = 0; e < 4; e++) acc1[mi][t][e] = 0.f;

#pragma unroll
    for (int s = 0; s < 6; s++) {
        uint32_t ah[2][4], al[2][4];
#pragma unroll
        for (int mi = 0; mi < 2; mi++) {
            int row = (wm + 4 * mi) * 16 + g;
            int base = row * A_ST + s * 8 + kp;
            ah[mi][0] = sw[WA_HI + base];
            ah[mi][1] = sw[WA_HI + base + 8 * A_ST];
            ah[mi][2] = sw[WA_HI + base + 4];
            ah[mi][3] = sw[WA_HI + base + 8 * A_ST + 4];
            al[mi][0] = sw[WA_LO + base];
            al[mi][1] = sw[WA_LO + base + 8 * A_ST];
            al[mi][2] = sw[WA_LO + base + 4];
            al[mi][3] = sw[WA_LO + base + 8 * A_ST + 4];
        }
#pragma unroll
        for (int t = 0; t < 4; t++) {
            int n = (wn * 4 + t) * 8 + g;
            int wb = n * W1_ST + s * 8 + kp;
            uint32_t bh[2] = { sw[WW1_HI + wb], sw[WW1_HI + wb + 4] };
            uint32_t bl[2] = { sw[WW1_LO + wb], sw[WW1_LO + wb + 4] };
#pragma unroll
            for (int mi = 0; mi < 2; mi++) {
                mma16816(acc1[mi][t], ah[mi], bh);
                mma16816(acc1[mi][t], ah[mi], bl);
                mma16816(acc1[mi][t], al[mi], bh);
            }
        }
    }

    // ---- epilogue 1: relu(+b1) -> H splits ----
#pragma unroll
    for (int mi = 0; mi < 2; mi++) {
        int r1 = (wm + 4 * mi) * 16 + g, r2 = r1 + 8;
#pragma unroll
        for (int t = 0; t < 4; t++) {
            int tile = wn * 4 + t;
            int c = tile * 8 + kp * 2;
            float bb0 = b1s[c], bb1 = b1s[c + 1];
            int wc = tile * 4 + kp;
            float v0 = fmaxf(acc1[mi][t][0] + bb0, 0.f);
            float v1 = fmaxf(acc1[mi][t][1] + bb1, 0.f);
            uint32_t whi, wlo;
            split_pair(v0, v1, whi, wlo);
            sw[WH_HI + r1 * H_ST + wc] = whi;
            sw[WH_LO + r1 * H_ST + wc] = wlo;
            float v2 = fmaxf(acc1[mi][t][2] + bb0, 0.f);
            float v3 = fmaxf(acc1[mi][t][3] + bb1, 0.f);
            split_pair(v2, v3, whi, wlo);
            sw[WH_HI + r2 * H_ST + wc] = whi;
            sw[WH_LO + r2 * H_ST + wc] = wlo;
        }
    }
    __syncthreads();

    // ---- GEMM2: two N-halves of 128, K=128 (8 k-steps) ----
    for (int nh = 0; nh < 2; nh++) {
        // stage W2[nh] over the dead A/W1 regions
        {
            const uint2* src = (const uint2*)(g_W2s + nh * 16384); // [hl][128][32 u2]
#pragma unroll
            for (int i = tid; i < 8192; i += 512) {
                int hl = i >> 12, rr = i & 4095;
                int n = rr >> 5, wq = rr & 31;
                *(uint2*)(sw + (hl ? WW2_LO : WW2_HI) + n * W2_ST + 2 * wq) = src[i];
            }
        }
        __syncthreads();

        float acc2[2][4][4];
#pragma unroll
        for (int mi = 0; mi < 2; mi++)
#pragma unroll
            for (int t = 0; t < 4; t++)
#pragma unroll
                for (int e = 0; e < 4; e++) acc2[mi][t][e] = 0.f;

#pragma unroll
        for (int s = 0; s < 8; s++) {
            uint32_t ah[2][4], al[2][4];
#pragma unroll
            for (int mi = 0; mi < 2; mi++) {
                int row = (wm + 4 * mi) * 16 + g;
                int base = row * H_ST + s * 8 + kp;
                ah[mi][0] = sw[WH_HI + base];
                ah[mi][1] = sw[WH_HI + base + 8 * H_ST];
                ah[mi][2] = sw[WH_HI + base + 4];
                ah[mi][3] = sw[WH_HI + base + 8 * H_ST + 4];
                al[mi][0] = sw[WH_LO + base];
                al[mi][1] = sw[WH_LO + base + 8 * H_ST];
                al[mi][2] = sw[WH_LO + base + 4];
                al[mi][3] = sw[WH_LO + base + 8 * H_ST + 4];
            }
#pragma unroll
            for (int t = 0; t < 4; t++) {
                int n = (wn * 4 + t) * 8 + g;
                int wb = n * W2_ST + s * 8 + kp;
                uint32_t bh[2] = { sw[WW2_HI + wb], sw[WW2_HI + wb + 4] };
                uint32_t bl[2] = { sw[WW2_LO + wb], sw[WW2_LO + wb + 4] };
#pragma unroll
                for (int mi = 0; mi < 2; mi++) {
                    mma16816(acc2[mi][t], ah[mi], bh);
                    mma16816(acc2[mi][t], ah[mi], bl);
                    mma16816(acc2[mi][t], al[mi], bh);
                }
            }
        }

        // ---- epilogue 2: +b2 -> out ----
#pragma unroll
        for (int mi = 0; mi < 2; mi++) {
            int r1 = (wm + 4 * mi) * 16 + g, r2 = r1 + 8;
#pragma unroll
            for (int t = 0; t < 4; t++) {
                int c = nh * 128 + (wn * 4 + t) * 8 + kp * 2;
                float bb0 = b2s[c], bb1 = b2s[c + 1];
                float2 v01 = make_float2(acc2[mi][t][0] + bb0, acc2[mi][t][1] + bb1);
                float2 v23 = make_float2(acc2[mi][t][2] + bb0, acc2[mi][t][3] + bb1);
                *(float2*)(out + (size_t)(n0 + r1) * 256 + c) = v01;
                *(float2*)(out + (size_t)(n0 + r2) * 256 + c) = v23;
            }
        }
        __syncthreads();   // all reads of W2 done before next stage overwrite
    }
}

// ---------------------------------------------------------------------------
extern "C" void kernel_launch(void* const* d_in, const int* in_sizes, int n_in,
                              void* d_out, int out_size)
{
    const float* x      = (const float*)d_in[0];
    const float* conv_w = (const float*)d_in[1];
    const float* conv_b = (const float*)d_in[2];
    const float* w1     = (const float*)d_in[3];
    const float* b1     = (const float*)d_in[4];
    const float* w2     = (const float*)d_in[5];
    const float* b2     = (const float*)d_in[6];
    float* out = (float*)d_out;

    (void)in_sizes; (void)n_in; (void)out_size;

    // Stage 1: double DWT -> g_F, plus weight split prologue in z-slice 6
    dim3 g1(HW / 256, B_DIM, 7);
    dwt_kernel<<<g1, 256>>>(x, w1, w2);

    // Stage 2: conv + HMMA MLP
    cudaFuncSetAttribute(mlp_kernel,
                         cudaFuncAttributeMaxDynamicSharedMemorySize, SMEM_BYTES);
    mlp_kernel<<<512, 512, SMEM_BYTES>>>(conv_w, conv_b, b1, b2, out);
}

// round 9
// speedup vs baseline: 2.9014x; 1.0309x over previous
#include <cuda_runtime.h>
#include <cuda_bf16.h>
#include <cstdint>

// ---------------------------------------------------------------------------
// ToFace_Unet_Dwt_locate — R9: HMMA bf16 3-term split + ldmatrix.x4 fragment
// loads + term-major MMA ordering (breaks same-acc RAW chains).
// ---------------------------------------------------------------------------

#define H0_0 0.48296291314469025f
#define H0_1 0.836516303737469f
#define H0_2 0.22414386804185735f
#define H0_3 (-0.12940952255092145f)
#define H1_0 0.12940952255092145f
#define H1_1 (-0.22414386804185735f)
#define H1_2 0.836516303737469f
#define H1_3 (-0.48296291314469025f)

#define B_DIM 16
#define C_IN 360
#define HW 4096
#define C_MID 180

// smem word (uint32) offsets
#define WB1    0                      // b1: 128 f32
#define WB2    128                    // b2: 256 f32
#define WA_HI  512                    // A hi  [128][52]
#define WA_LO  7168                   // A lo  [128][52]
#define WW1_HI 13824                  // W1 hi [128][52]
#define WW1_LO 20480                  // W1 lo [128][52]
#define WW2_HI 512                    // W2 stage hi [128][68] (aliases A)
#define WW2_LO 9216                   // W2 stage lo [128][68] (aliases A/W1)
#define WH_HI  27136                  // H hi [128][68]; also F staging earlier
#define WH_LO  35840                  // H lo [128][68]
#define SMEM_WORDS 44544
#define SMEM_BYTES (SMEM_WORDS * 4)   // 178176

#define A_ST  52
#define W1_ST 52
#define W2_ST 68
#define H_ST  68

__device__ float g_F[(size_t)B_DIM * C_MID * HW];   // 47.2 MB scratch
__device__ uint32_t g_W1s[12288];                   // [hl][128][48 words]
__device__ uint32_t g_W2s[32768];                   // [nh][hl][128][64 words]

// ---- helpers --------------------------------------------------------------
__device__ __forceinline__ uint32_t pack_bf16(__nv_bfloat16 lo, __nv_bfloat16 hi) {
    return ((uint32_t)__bfloat16_as_ushort(hi) << 16) | __bfloat16_as_ushort(lo);
}
__device__ __forceinline__ void split_pair(float v0, float v1,
                                           uint32_t& whi, uint32_t& wlo) {
    __nv_bfloat16 h0 = __float2bfloat16(v0);
    __nv_bfloat16 h1 = __float2bfloat16(v1);
    float r0 = v0 - __bfloat162float(h0);
    float r1 = v1 - __bfloat162float(h1);
    whi = pack_bf16(h0, h1);
    wlo = pack_bf16(__float2bfloat16(r0), __float2bfloat16(r1));
}
__device__ __forceinline__ uint32_t split_word(float v0, float v1, int hl) {
    uint32_t a, b;
    split_pair(v0, v1, a, b);
    return hl ? b : a;
}
__device__ __forceinline__ void mma16816(float* d, const uint32_t* a,
                                         const uint32_t* b) {
    asm volatile(
        "mma.sync.aligned.m16n8k16.row.col.f32.bf16.bf16.f32 "
        "{%0,%1,%2,%3}, {%4,%5,%6,%7}, {%8,%9}, {%0,%1,%2,%3};"
        : "+f"(d[0]), "+f"(d[1]), "+f"(d[2]), "+f"(d[3])
        : "r"(a[0]), "r"(a[1]), "r"(a[2]), "r"(a[3]), "r"(b[0]), "r"(b[1]));
}
__device__ __forceinline__ void ldsm4(uint32_t* r, uint32_t saddr) {
    asm volatile("ldmatrix.sync.aligned.m8n8.x4.shared.b16 {%0,%1,%2,%3}, [%4];"
                 : "=r"(r[0]), "=r"(r[1]), "=r"(r[2]), "=r"(r[3]) : "r"(saddr));
}

// ---------------------------------------------------------------------------
// Kernel 1: DWT (z 0..5) + weight split prologue (z == 6). grid (16,16,7)x256.
// ---------------------------------------------------------------------------
__global__ void __launch_bounds__(256) dwt_kernel(const float* __restrict__ X,
                                                  const float* __restrict__ w1,
                                                  const float* __restrict__ w2)
{
    if (blockIdx.z == 6) {
        int i = (blockIdx.y * 16 + blockIdx.x) * 256 + threadIdx.x;
        if (i < 12288) {                 // W1 words: [hl][n 128][wd 48]
            int hl = i / 6144, rr = i % 6144;
            int n = rr / 48, wd = rr % 48;
            int k0 = 2 * wd;
            float v0 = (k0     < 90) ? w1[n * 90 + k0]     : 0.f;
            float v1 = (k0 + 1 < 90) ? w1[n * 90 + k0 + 1] : 0.f;
            g_W1s[i] = split_word(v0, v1, hl);
        } else if (i < 12288 + 32768) {  // W2 words: [nh][hl][n 128][wd 64]
            int j = i - 12288;
            int nh = j >> 14, r2 = j & 16383;
            int hl = r2 >> 13, r3 = r2 & 8191;
            int n = r3 >> 6, wd = r3 & 63;
            int ng = nh * 128 + n, k0 = 2 * wd;
            float v0 = w2[ng * 128 + k0];
            float v1 = w2[ng * 128 + k0 + 1];
            g_W2s[j] = split_word(v0, v1, hl);
        }
        return;
    }

    const int hw = blockIdx.x * 256 + threadIdx.x;
    const int b  = blockIdx.y;
    const int c0 = blockIdx.z * 15;

    const float* Xp = X + (size_t)b * C_IN * HW + hw;

    const int jstart = 2 * c0 - 2;
    float h1v[32];

    int j = jstart;
    int cA = 2 * j - 2, cB = 2 * j - 1;
    float xm2 = (cA >= 0 && cA < C_IN) ? Xp[(size_t)cA * HW] : 0.f;
    float xm1 = (cB >= 0 && cB < C_IN) ? Xp[(size_t)cB * HW] : 0.f;
#pragma unroll
    for (int t = 0; t < 32; t++) {
        int c2j = 2 * j, c2j1 = 2 * j + 1;
        float x0 = (c2j  >= 0 && c2j  < C_IN) ? Xp[(size_t)c2j  * HW] : 0.f;
        float x1 = (c2j1 >= 0 && c2j1 < C_IN) ? Xp[(size_t)c2j1 * HW] : 0.f;
        float h = 0.f;
        if (j >= 0 && j < 180)
            h = H1_0 * xm2 + H1_1 * xm1 + H1_2 * x0 + H1_3 * x1;
        h1v[t] = h;
        xm2 = x0; xm1 = x1; j++;
    }

    float* Fp = g_F + (size_t)b * C_MID * HW + hw;
#pragma unroll
    for (int u = 0; u < 15; u++) {
        int c2 = c0 + u;
        float a = h1v[2 * u], bb = h1v[2 * u + 1], cc = h1v[2 * u + 2], dd = h1v[2 * u + 3];
        float lo = H0_0 * a + H0_1 * bb + H0_2 * cc + H0_3 * dd;
        float hi = H1_0 * a + H1_1 * bb + H1_2 * cc + H1_3 * dd;
        Fp[(size_t)c2 * HW]        = lo;
        Fp[(size_t)(90 + c2) * HW] = hi;
    }
}

// ---------------------------------------------------------------------------
// Kernel 2: HMMA conv+MLP. 512 blocks x 512 threads, 128 chunks/block.
// ---------------------------------------------------------------------------
__global__ void __launch_bounds__(512) mlp_kernel(
    const float* __restrict__ cw, const float* __restrict__ cbp,
    const float* __restrict__ b1, const float* __restrict__ b2,
    float* __restrict__ out)
{
    extern __shared__ uint32_t sw[];
    float* b1s = (float*)(sw + WB1);
    float* b2s = (float*)(sw + WB2);
    const uint32_t swb = (uint32_t)__cvta_generic_to_shared(sw);

    const int tid = threadIdx.x;
    const int n0  = blockIdx.x * 128;
    const int w   = tid >> 5, l = tid & 31;
    const int wm  = w & 3, wn = w >> 2;      // 4 m-warps x 4 n-warps
    const int g   = l >> 2, kp = l & 3;      // fragment row group / k-pair lane

    // ldmatrix lane address components
    const int a_lrow = l & 15;               // A: row within 16-row tile
    const int a_lcol = (l >> 4) * 4;         // A: word-col offset (0 or 4)
    const int b_sel  = l >> 3, b_r8 = l & 7; // B: matrix select / row
    const int b_tof  = (b_sel >> 1);         // B: which tile of the pair
    const int b_col  = (b_sel & 1) * 4;      // B: word-col offset

    // ---- biases + W1 stage copy ----
    if (tid < 128) b1s[tid] = b1[tid];
    if (tid < 256) b2s[tid] = b2[tid];
    {
        const uint2* src = (const uint2*)g_W1s;   // [hl][128][24 uint2]
#pragma unroll
        for (int i = tid; i < 6144; i += 512) {
            int hl = i / 3072, rr = i % 3072;
            int n = rr / 24, wq = rr % 24;
            *(uint2*)(sw + (hl ? WW1_LO : WW1_HI) + n * W1_ST + 2 * wq) = src[i];
        }
    }

    // ---- conv: F staged through H region, 2 halves of 64 chunks ----
    {
        float c0w[7], c1w[7];
#pragma unroll
        for (int i = 0; i < 7; i++) { c0w[i] = cw[i]; c1w[i] = cw[7 + i]; }
        const float cb = cbp[0];
        float* sF = (float*)(sw + WH_HI);
        const int ml = tid >> 3, q8 = tid & 7;

        for (int fh = 0; fh < 2; fh++) {
            const float4* src = (const float4*)(g_F + (size_t)(n0 + fh * 64) * 180);
            float4* dst = (float4*)sF;
#pragma unroll
            for (int i = tid; i < 2880; i += 512) dst[i] = src[i];
            __syncthreads();

            const float* r0 = sF + ml * 180;
            const float* r1 = r0 + 90;
            float a0[18], a1[18];
#pragma unroll
            for (int t = 0; t < 18; t++) {
                int idx = q8 * 12 - 3 + t;
                bool ok = (idx >= 0 && idx < 90);
                a0[t] = ok ? r0[idx] : 0.f;
                a1[t] = ok ? r1[idx] : 0.f;
            }
            const int mrow = fh * 64 + ml;
            uint32_t* Ah = sw + WA_HI + mrow * A_ST;
            uint32_t* Al = sw + WA_LO + mrow * A_ST;
#pragma unroll
            for (int pl = 0; pl < 6; pl++) {
                int p = q8 * 6 + pl;
                float v0 = 0.f, v1 = 0.f;
                if (2 * p < 90) {
                    float s0 = cb, s1 = cb;
#pragma unroll
                    for (int kw = 0; kw < 7; kw++) {
                        s0 += c0w[kw] * a0[2 * pl + kw]     + c1w[kw] * a1[2 * pl + kw];
                        s1 += c0w[kw] * a0[2 * pl + 1 + kw] + c1w[kw] * a1[2 * pl + 1 + kw];
                    }
                    v0 = fmaxf(s0, 0.f);
                    v1 = fmaxf(s1, 0.f);
                }
                uint32_t whi, wlo;
                split_pair(v0, v1, whi, wlo);
                Ah[p] = whi;
                Al[p] = wlo;
            }
            __syncthreads();
        }
    }

    // ---- GEMM1: [128m x 128n], K=96 (6 k-steps), 3-term, term-major ----
    float acc1[2][4][4];
#pragma unroll
    for (int mi = 0; mi < 2; mi++)
#pragma unroll
        for (int t = 0; t < 4; t++)
#pragma unroll
            for (int e = 0; e < 4; e++) acc1[mi][t][e] = 0.f;

    {
        uint32_t aHi[2], aLo[2], bHi[2], bLo[2];
#pragma unroll
        for (int mi = 0; mi < 2; mi++) {
            int row = (wm + 4 * mi) * 16 + a_lrow;
            aHi[mi] = swb + 4 * (WA_HI + row * A_ST + a_lcol);
            aLo[mi] = swb + 4 * (WA_LO + row * A_ST + a_lcol);
        }
#pragma unroll
        for (int tp = 0; tp < 2; tp++) {
            int n = (wn * 4 + 2 * tp + b_tof) * 8 + b_r8;
            bHi[tp] = swb + 4 * (WW1_HI + n * W1_ST + b_col);
            bLo[tp] = swb + 4 * (WW1_LO + n * W1_ST + b_col);
        }

#pragma unroll
        for (int s = 0; s < 6; s++) {
            uint32_t ah[2][4], al[2][4], bh[2][4], bl[2][4];
            const uint32_t so = s * 32;
            ldsm4(ah[0], aHi[0] + so); ldsm4(ah[1], aHi[1] + so);
            ldsm4(al[0], aLo[0] + so); ldsm4(al[1], aLo[1] + so);
            ldsm4(bh[0], bHi[0] + so); ldsm4(bh[1], bHi[1] + so);
            ldsm4(bl[0], bLo[0] + so); ldsm4(bl[1], bLo[1] + so);
#pragma unroll
            for (int t = 0; t < 4; t++)
#pragma unroll
                for (int mi = 0; mi < 2; mi++)
                    mma16816(acc1[mi][t], ah[mi], &bh[t >> 1][(t & 1) * 2]);
#pragma unroll
            for (int t = 0; t < 4; t++)
#pragma unroll
                for (int mi = 0; mi < 2; mi++)
                    mma16816(acc1[mi][t], ah[mi], &bl[t >> 1][(t & 1) * 2]);
#pragma unroll
            for (int t = 0; t < 4; t++)
#pragma unroll
                for (int mi = 0; mi < 2; mi++)
                    mma16816(acc1[mi][t], al[mi], &bh[t >> 1][(t & 1) * 2]);
        }
    }

    // ---- epilogue 1: relu(+b1) -> H splits ----
#pragma unroll
    for (int mi = 0; mi < 2; mi++) {
        int r1 = (wm + 4 * mi) * 16 + g, r2 = r1 + 8;
#pragma unroll
        for (int t = 0; t < 4; t++) {
            int tile = wn * 4 + t;
            int c = tile * 8 + kp * 2;
            float bb0 = b1s[c], bb1 = b1s[c + 1];
            int wc = tile * 4 + kp;
            float v0 = fmaxf(acc1[mi][t][0] + bb0, 0.f);
            float v1 = fmaxf(acc1[mi][t][1] + bb1, 0.f);
            uint32_t whi, wlo;
            split_pair(v0, v1, whi, wlo);
            sw[WH_HI + r1 * H_ST + wc] = whi;
            sw[WH_LO + r1 * H_ST + wc] = wlo;
            float v2 = fmaxf(acc1[mi][t][2] + bb0, 0.f);
            float v3 = fmaxf(acc1[mi][t][3] + bb1, 0.f);
            split_pair(v2, v3, whi, wlo);
            sw[WH_HI + r2 * H_ST + wc] = whi;
            sw[WH_LO + r2 * H_ST + wc] = wlo;
        }
    }
    __syncthreads();

    // ---- GEMM2: two N-halves of 128, K=128 (8 k-steps) ----
    uint32_t hHi[2], hLo[2];
#pragma unroll
    for (int mi = 0; mi < 2; mi++) {
        int row = (wm + 4 * mi) * 16 + a_lrow;
        hHi[mi] = swb + 4 * (WH_HI + row * H_ST + a_lcol);
        hLo[mi] = swb + 4 * (WH_LO + row * H_ST + a_lcol);
    }
    uint32_t w2Hi[2], w2Lo[2];
#pragma unroll
    for (int tp = 0; tp < 2; tp++) {
        int n = (wn * 4 + 2 * tp + b_tof) * 8 + b_r8;
        w2Hi[tp] = swb + 4 * (WW2_HI + n * W2_ST + b_col);
        w2Lo[tp] = swb + 4 * (WW2_LO + n * W2_ST + b_col);
    }

    for (int nh = 0; nh < 2; nh++) {
        // stage W2[nh] over the dead A/W1 regions
        {
            const uint2* src = (const uint2*)(g_W2s + nh * 16384); // [hl][128][32 u2]
#pragma unroll
            for (int i = tid; i < 8192; i += 512) {
                int hl = i >> 12, rr = i & 4095;
                int n = rr >> 5, wq = rr & 31;
                *(uint2*)(sw + (hl ? WW2_LO : WW2_HI) + n * W2_ST + 2 * wq) = src[i];
            }
        }
        __syncthreads();

        float acc2[2][4][4];
#pragma unroll
        for (int mi = 0; mi < 2; mi++)
#pragma unroll
            for (int t = 0; t < 4; t++)
#pragma unroll
                for (int e = 0; e < 4; e++) acc2[mi][t][e] = 0.f;

#pragma unroll
        for (int s = 0; s < 8; s++) {
            uint32_t ah[2][4], al[2][4], bh[2][4], bl[2][4];
            const uint32_t so = s * 32;
            ldsm4(ah[0], hHi[0] + so);  ldsm4(ah[1], hHi[1] + so);
            ldsm4(al[0], hLo[0] + so);  ldsm4(al[1], hLo[1] + so);
            ldsm4(bh[0], w2Hi[0] + so); ldsm4(bh[1], w2Hi[1] + so);
            ldsm4(bl[0], w2Lo[0] + so); ldsm4(bl[1], w2Lo[1] + so);
#pragma unroll
            for (int t = 0; t < 4; t++)
#pragma unroll
                for (int mi = 0; mi < 2; mi++)
                    mma16816(acc2[mi][t], ah[mi], &bh[t >> 1][(t & 1) * 2]);
#pragma unroll
            for (int t = 0; t < 4; t++)
#pragma unroll
                for (int mi = 0; mi < 2; mi++)
                    mma16816(acc2[mi][t], ah[mi], &bl[t >> 1][(t & 1) * 2]);
#pragma unroll
            for (int t = 0; t < 4; t++)
#pragma unroll
                for (int mi = 0; mi < 2; mi++)
                    mma16816(acc2[mi][t], al[mi], &bh[t >> 1][(t & 1) * 2]);
        }

        // ---- epilogue 2: +b2 -> out ----
#pragma unroll
        for (int mi = 0; mi < 2; mi++) {
            int r1 = (wm + 4 * mi) * 16 + g, r2 = r1 + 8;
#pragma unroll
            for (int t = 0; t < 4; t++) {
                int c = nh * 128 + (wn * 4 + t) * 8 + kp * 2;
                float bb0 = b2s[c], bb1 = b2s[c + 1];
                float2 v01 = make_float2(acc2[mi][t][0] + bb0, acc2[mi][t][1] + bb1);
                float2 v23 = make_float2(acc2[mi][t][2] + bb0, acc2[mi][t][3] + bb1);
                *(float2*)(out + (size_t)(n0 + r1) * 256 + c) = v01;
                *(float2*)(out + (size_t)(n0 + r2) * 256 + c) = v23;
            }
        }
        __syncthreads();   // all reads of W2 done before next stage overwrite
    }
}

// ---------------------------------------------------------------------------
extern "C" void kernel_launch(void* const* d_in, const int* in_sizes, int n_in,
                              void* d_out, int out_size)
{
    const float* x      = (const float*)d_in[0];
    const float* conv_w = (const float*)d_in[1];
    const float* conv_b = (const float*)d_in[2];
    const float* w1     = (const float*)d_in[3];
    const float* b1     = (const float*)d_in[4];
    const float* w2     = (const float*)d_in[5];
    const float* b2     = (const float*)d_in[6];
    float* out = (float*)d_out;

    (void)in_sizes; (void)n_in; (void)out_size;

    // Stage 1: double DWT -> g_F, plus weight split prologue in z-slice 6
    dim3 g1(HW / 256, B_DIM, 7);
    dwt_kernel<<<g1, 256>>>(x, w1, w2);

    // Stage 2: conv + HMMA MLP
    cudaFuncSetAttribute(mlp_kernel,
                         cudaFuncAttributeMaxDynamicSharedMemorySize, SMEM_BYTES);
    mlp_kernel<<<512, 512, SMEM_BYTES>>>(conv_w, conv_b, b1, b2, out);
}